// round 1
// baseline (speedup 1.0000x reference)
#include <cuda_runtime.h>
#include <cstdint>

// Problem constants
#define NROWS   65536      // BS*H*W = 16*64*64
#define KCODES  512
#define DDIM    64
#define HW      4096       // H*W
#define TPB     256
#define NCTA    (NROWS / TPB)   // 256

#define Z_ELEMS  (NROWS * DDIM)        // 4194304
#define IDX_OFF  Z_ELEMS               // indices start
#define KL_OFF   (Z_ELEMS + NROWS)     // 4259840
#define CM_OFF   (KL_OFF + 1)

#define LOG_K    6.2383246250395077f   // ln(512)
#define NEG_BIG  (-3.402823466e38f)

// deterministic cross-CTA reduction scratch
__device__ float g_kl_partials[NCTA];
__device__ float g_cm_partials[NCTA];

__global__ __launch_bounds__(TPB, 1)
void vq_main(const float* __restrict__ ze,
             const float* __restrict__ cb,
             const float* __restrict__ u,
             float* __restrict__ out)
{
    extern __shared__ float smem[];
    float* sc  = smem;                    // codebook [512][64]
    float* scn = smem + KCODES * DDIM;    // cnorm [512]
    __shared__ float rbuf[16];

    // cooperative codebook load (vectorized, coalesced)
    {
        float4*       dst = (float4*)sc;
        const float4* src = (const float4*)cb;
        #pragma unroll 4
        for (int i = threadIdx.x; i < KCODES * DDIM / 4; i += TPB) dst[i] = src[i];
    }
    __syncthreads();
    // codebook norms
    for (int k = threadIdx.x; k < KCODES; k += TPB) {
        const float4* row = (const float4*)(sc + k * DDIM);
        float acc = 0.f;
        #pragma unroll
        for (int i = 0; i < DDIM / 4; i++) {
            float4 v = row[i];
            acc += v.x * v.x + v.y * v.y + v.z * v.z + v.w * v.w;
        }
        scn[k] = acc;
    }
    __syncthreads();

    const int n  = blockIdx.x * TPB + threadIdx.x;
    const int b  = n >> 12;       // n / 4096
    const int hw = n & 4095;

    // load ze row (transposed access, coalesced across warp)
    const float* zp = ze + (size_t)b * (DDIM * HW) + hw;
    float z[DDIM];
    float zn = 0.f;
    #pragma unroll
    for (int dd = 0; dd < DDIM; dd++) {
        z[dd] = zp[(size_t)dd * HW];
        zn = fmaf(z[dd], z[dd], zn);
    }

    float zq[DDIM];
    #pragma unroll
    for (int dd = 0; dd < DDIM; dd++) zq[dd] = 0.f;

    const float4* urow = (const float4*)(u + (size_t)n * KCODES);

    // online softmax state: soft (gumbel, temp) and probs
    float m1 = NEG_BIG, L1 = 0.f;
    float m2 = NEG_BIG, L2 = 0.f, S2 = 0.f;
    float best = NEG_BIG;
    int   bidx = 0;

    #pragma unroll 4
    for (int k = 0; k < KCODES; k++) {
        float4 uv;
        float uu;
        {
            // fetch u in float4 granularity; (k&3) is compile-time under unroll 4
            if ((k & 3) == 0) uv = urow[k >> 2];
            static float4 uv_keep; // never used; placeholder removed below
            (void)0;
            if ((k & 3) == 0)      uu = uv.x;
            else if ((k & 3) == 1) uu = uv.y;
            else if ((k & 3) == 2) uu = uv.z;
            else                   uu = uv.w;
        }

        const float4* crow = (const float4*)(sc + k * DDIM);

        // dot(z, c_k) with 4-way ILP
        float d0 = 0.f, d1 = 0.f, d2 = 0.f, d3 = 0.f;
        #pragma unroll
        for (int i = 0; i < DDIM / 4; i++) {
            float4 c4 = crow[i];
            d0 = fmaf(z[4 * i + 0], c4.x, d0);
            d1 = fmaf(z[4 * i + 1], c4.y, d1);
            d2 = fmaf(z[4 * i + 2], c4.z, d2);
            d3 = fmaf(z[4 * i + 3], c4.w, d3);
        }
        float dot = (d0 + d1) + (d2 + d3);

        // logit l = -(cn + zn - 2 dot)
        float l = fmaf(2.f, dot, -(scn[k] + zn));

        // gumbel: -log(-log(u + 1e-10) + 1e-10)
        float t1 = logf(uu + 1e-10f);           // negative
        float g  = -logf(1e-10f - t1);
        float s  = 2.f * (l + g);               // (l+g)/T, T=0.5

        // hard argmax on s (first-max kept via strict >)
        if (s > best) { best = s; bidx = k; }

        // probs softmax (scalar accumulators, branchless rescale)
        float mn2 = fmaxf(m2, l);
        float c2  = expf(m2 - mn2);
        float e2  = expf(l - mn2);
        L2 = fmaf(L2, c2, e2);
        S2 = fmaf(S2, c2, l * e2);
        m2 = mn2;

        // soft softmax + z_q accumulation (rare rescale branch)
        float p;
        if (s > m1) {
            float c1 = expf(m1 - s);
            L1 *= c1;
            #pragma unroll
            for (int dd = 0; dd < DDIM; dd++) zq[dd] *= c1;
            m1 = s;
            p  = 1.f;
        } else {
            p = expf(s - m1);
        }
        L1 += p;
        #pragma unroll
        for (int i = 0; i < DDIM / 4; i++) {
            float4 c4 = crow[i];
            zq[4 * i + 0] = fmaf(p, c4.x, zq[4 * i + 0]);
            zq[4 * i + 1] = fmaf(p, c4.y, zq[4 * i + 1]);
            zq[4 * i + 2] = fmaf(p, c4.z, zq[4 * i + 2]);
            zq[4 * i + 3] = fmaf(p, c4.w, zq[4 * i + 3]);
        }
    }

    // z_q output: [bs, d, h, w] (coalesced per dd across warp)
    float invL1 = 1.f / L1;
    float* oq = out + (size_t)b * (DDIM * HW) + hw;
    #pragma unroll
    for (int dd = 0; dd < DDIM; dd++) oq[(size_t)dd * HW] = zq[dd] * invL1;

    // hard index as float
    out[IDX_OFF + n] = (float)bidx;

    // per-row KL / commit via identity:
    //   sum_k p*(log p + logK) = S2/L2 - m2 - log(L2) + logK
    //   sum_k p*dist           = -S2/L2
    float Epl    = S2 / L2;
    float kl_row = Epl - m2 - logf(L2) + LOG_K;
    float cm_row = -Epl;

    // deterministic CTA reduction
    #pragma unroll
    for (int off = 16; off > 0; off >>= 1) {
        kl_row += __shfl_xor_sync(0xFFFFFFFFu, kl_row, off);
        cm_row += __shfl_xor_sync(0xFFFFFFFFu, cm_row, off);
    }
    int wid  = threadIdx.x >> 5;
    int lane = threadIdx.x & 31;
    if (lane == 0) { rbuf[wid] = kl_row; rbuf[8 + wid] = cm_row; }
    __syncthreads();
    if (threadIdx.x == 0) {
        float a = 0.f, c = 0.f;
        #pragma unroll
        for (int w = 0; w < 8; w++) { a += rbuf[w]; c += rbuf[8 + w]; }
        g_kl_partials[blockIdx.x] = a;
        g_cm_partials[blockIdx.x] = c;
    }
}

__global__ __launch_bounds__(TPB)
void vq_finalize(float* __restrict__ out)
{
    __shared__ float rbuf[16];
    int t = threadIdx.x;
    float a = g_kl_partials[t];
    float c = g_cm_partials[t];
    #pragma unroll
    for (int off = 16; off > 0; off >>= 1) {
        a += __shfl_xor_sync(0xFFFFFFFFu, a, off);
        c += __shfl_xor_sync(0xFFFFFFFFu, c, off);
    }
    int wid  = t >> 5;
    int lane = t & 31;
    if (lane == 0) { rbuf[wid] = a; rbuf[8 + wid] = c; }
    __syncthreads();
    if (t == 0) {
        float ka = 0.f, ca = 0.f;
        #pragma unroll
        for (int w = 0; w < 8; w++) { ka += rbuf[w]; ca += rbuf[8 + w]; }
        out[KL_OFF] = ka * (1.f / 16.f);   // mean over batch
        out[CM_OFF] = ca * (1.f / 16.f);
    }
}

extern "C" void kernel_launch(void* const* d_in, const int* in_sizes, int n_in,
                              void* d_out, int out_size)
{
    const float* ze = (const float*)d_in[0];
    const float* cb = (const float*)d_in[1];
    const float* u  = (const float*)d_in[2];
    float* out = (float*)d_out;

    const int smem_bytes = (KCODES * DDIM + KCODES) * (int)sizeof(float); // 133120
    cudaFuncSetAttribute(vq_main, cudaFuncAttributeMaxDynamicSharedMemorySize, smem_bytes);

    vq_main<<<NCTA, TPB, smem_bytes>>>(ze, cb, u, out);
    vq_finalize<<<1, TPB>>>(out);
}